// round 2
// baseline (speedup 1.0000x reference)
#include <cuda_runtime.h>
#include <cuda_bf16.h>

#define BB 64
#define NN 2048
#define DD 1024
#define SPLIT 32
#define ROWS_BLK (NN / SPLIT)        // 64 rows per block
#define RSTAGE 8                     // rows per pipeline stage (== warps)
#define NSTAGES (ROWS_BLK / RSTAGE)  // 8
#define SBUF 3                       // pipeline depth
#define ESPLIT 4

#define SMEM_K1 (SBUF * RSTAGE * DD * 4)  // 98304 bytes

// Scratch (static device globals; no allocation)
__device__ float g_scores[BB * NN];
__device__ float g_part_m[BB * SPLIT];
__device__ float g_part_l[BB * SPLIT];
__device__ float g_part_mix[BB * SPLIT * DD];  // un-normalized partial mix (8 MB)
__device__ float g_comb[BB * 2 * DD];          // [mix | output]
__device__ float g_out_part[ESPLIT * BB * DD]; // GEMM e-split partials

__device__ __forceinline__ unsigned smem_u32(const void* p) {
    return (unsigned)__cvta_generic_to_shared(p);
}

// ---------------------------------------------------------------------------
// Kernel 1: cp.async-pipelined scores + online softmax + mix accumulation.
// grid (SPLIT, BB), 256 threads (8 warps). Warp w computes row w of each
// 8-row stage. 3-stage ring buffer in dynamic smem keeps ~128KB/SM in flight.
// ---------------------------------------------------------------------------
__global__ __launch_bounds__(256, 2)
void k1_scores_mix(const float* __restrict__ output,
                   const float* __restrict__ context) {
    extern __shared__ float tile[];          // SBUF * RSTAGE * DD floats
    __shared__ float sm[8], sl[8];

    const int split = blockIdx.x;
    const int b     = blockIdx.y;
    const int tid   = threadIdx.x;
    const int w     = tid >> 5;
    const int lane  = tid & 31;

    const float* q   = output + (size_t)b * DD;
    const float* ctx = context + (size_t)b * NN * DD
                               + (size_t)(split * ROWS_BLK) * DD;

    // Query slice in registers: lane covers cols {j*128 + lane*4 .. +3}
    float4 qv[8];
#pragma unroll
    for (int j = 0; j < 8; j++)
        qv[j] = *(const float4*)(q + j * 128 + lane * 4);

    float acc[32];
#pragma unroll
    for (int k = 0; k < 32; k++) acc[k] = 0.f;
    float m = -1e30f, l = 0.f;

    // ---- pipeline prologue: issue first SBUF-1 stages ----
#pragma unroll
    for (int ps = 0; ps < SBUF - 1; ps++) {
        float* dst = tile + (ps % SBUF) * (RSTAGE * DD);
        const float* src = ctx + (size_t)ps * RSTAGE * DD;
#pragma unroll
        for (int i = 0; i < 8; i++) {
            int off = (i * 256 + tid) * 4;
            unsigned sa = smem_u32(dst + off);
            asm volatile("cp.async.cg.shared.global [%0], [%1], 16;\n"
                         :: "r"(sa), "l"(src + off));
        }
        asm volatile("cp.async.commit_group;\n");
    }

    for (int ks = 0; ks < NSTAGES; ks++) {
        asm volatile("cp.async.wait_group 1;\n");
        __syncthreads();

        // ---- compute on stage ks ----
        const float* row = tile + (ks % SBUF) * (RSTAGE * DD) + w * DD;
        float4 cv[8];
#pragma unroll
        for (int j = 0; j < 8; j++)
            cv[j] = *(const float4*)(row + j * 128 + lane * 4);

        float s0 = 0.f, s1 = 0.f, s2 = 0.f, s3 = 0.f;
#pragma unroll
        for (int j = 0; j < 8; j++) {
            s0 = fmaf(qv[j].x, cv[j].x, s0);
            s1 = fmaf(qv[j].y, cv[j].y, s1);
            s2 = fmaf(qv[j].z, cv[j].z, s2);
            s3 = fmaf(qv[j].w, cv[j].w, s3);
        }
        float s = (s0 + s1) + (s2 + s3);
#pragma unroll
        for (int off = 16; off; off >>= 1)
            s += __shfl_xor_sync(0xffffffffu, s, off);

        if (lane == 0)
            g_scores[(size_t)b * NN + split * ROWS_BLK + ks * RSTAGE + w] = s;

        // Branchy online softmax (s is warp-uniform: no divergence).
        if (s <= m) {
            const float p = __expf(s - m);
            l += p;
#pragma unroll
            for (int j = 0; j < 8; j++) {
                acc[4 * j + 0] = fmaf(p, cv[j].x, acc[4 * j + 0]);
                acc[4 * j + 1] = fmaf(p, cv[j].y, acc[4 * j + 1]);
                acc[4 * j + 2] = fmaf(p, cv[j].z, acc[4 * j + 2]);
                acc[4 * j + 3] = fmaf(p, cv[j].w, acc[4 * j + 3]);
            }
        } else {
            const float c = __expf(m - s);
            l = fmaf(l, c, 1.f);
#pragma unroll
            for (int j = 0; j < 8; j++) {
                acc[4 * j + 0] = fmaf(acc[4 * j + 0], c, cv[j].x);
                acc[4 * j + 1] = fmaf(acc[4 * j + 1], c, cv[j].y);
                acc[4 * j + 2] = fmaf(acc[4 * j + 2], c, cv[j].z);
                acc[4 * j + 3] = fmaf(acc[4 * j + 3], c, cv[j].w);
            }
            m = s;
        }

        __syncthreads();

        // ---- issue stage ks + SBUF - 1 ----
        const int ns = ks + SBUF - 1;
        if (ns < NSTAGES) {
            float* dst = tile + (ns % SBUF) * (RSTAGE * DD);
            const float* src = ctx + (size_t)ns * RSTAGE * DD;
#pragma unroll
            for (int i = 0; i < 8; i++) {
                int off = (i * 256 + tid) * 4;
                unsigned sa = smem_u32(dst + off);
                asm volatile("cp.async.cg.shared.global [%0], [%1], 16;\n"
                             :: "r"(sa), "l"(src + off));
            }
        }
        asm volatile("cp.async.commit_group;\n");
    }

    // ---- block combine (tree reduce through smem, no atomics) ----
    if (lane == 0) { sm[w] = m; sl[w] = l; }
    __syncthreads();

    float M = sm[0];
#pragma unroll
    for (int s2 = 1; s2 < 8; s2++) M = fmaxf(M, sm[s2]);
    float L = 0.f;
#pragma unroll
    for (int s2 = 0; s2 < 8; s2++) L += sl[s2] * __expf(sm[s2] - M);

    const float scale = __expf(m - M);  // m uniform within warp
    float* red = tile;                  // reuse: 8 * DD floats
#pragma unroll
    for (int j = 0; j < 8; j++) {
        float4 v = make_float4(acc[4 * j + 0] * scale, acc[4 * j + 1] * scale,
                               acc[4 * j + 2] * scale, acc[4 * j + 3] * scale);
        *(float4*)(red + w * DD + j * 128 + lane * 4) = v;
    }
    __syncthreads();

    // 256 threads x 4 floats = 1024: sum the 8 warp slices
    {
        const int d0 = tid * 4;
        float4 r = *(const float4*)(red + d0);
#pragma unroll
        for (int ww = 1; ww < 8; ww++) {
            float4 v = *(const float4*)(red + ww * DD + d0);
            r.x += v.x; r.y += v.y; r.z += v.z; r.w += v.w;
        }
        const int ps = b * SPLIT + split;
        *(float4*)(&g_part_mix[(size_t)ps * DD + d0]) = r;
        if (tid == 0) { g_part_m[ps] = M; g_part_l[ps] = L; }
    }
}

// ---------------------------------------------------------------------------
// Kernel 2: combine splits -> final mix; build [mix|output]; write attn
// ---------------------------------------------------------------------------
__global__ void k2_combine(const float* __restrict__ output,
                           float* __restrict__ attn_out) {
    const int b   = blockIdx.x;
    const int tid = threadIdx.x;

    float M = -1e30f;
#pragma unroll
    for (int s = 0; s < SPLIT; s++) M = fmaxf(M, g_part_m[b * SPLIT + s]);
    float L = 0.f;
#pragma unroll
    for (int s = 0; s < SPLIT; s++)
        L += g_part_l[b * SPLIT + s] * __expf(g_part_m[b * SPLIT + s] - M);
    const float invL = 1.f / L;

    for (int d = tid; d < DD; d += blockDim.x) {
        float a = 0.f;
#pragma unroll
        for (int s = 0; s < SPLIT; s++)
            a += g_part_mix[(size_t)(b * SPLIT + s) * DD + d] *
                 __expf(g_part_m[b * SPLIT + s] - M);
        g_comb[(size_t)b * 2 * DD + d] = a * invL;
    }
    for (int d = tid; d < DD; d += blockDim.x)
        g_comb[(size_t)b * 2 * DD + DD + d] = output[(size_t)b * DD + d];
    for (int n = tid; n < NN; n += blockDim.x)
        attn_out[(size_t)b * NN + n] =
            __expf(g_scores[(size_t)b * NN + n] - M) * invL;
}

// ---------------------------------------------------------------------------
// Kernel 3: out_part = comb @ W^T, tiled. Block: 32 d x 64 b x 512 e.
// ---------------------------------------------------------------------------
__global__ __launch_bounds__(128)
void k3_gemm(const float* __restrict__ W) {
    const int dt  = blockIdx.x;
    const int es  = blockIdx.y;
    const int tid = threadIdx.x;
    const int d0  = dt * 32;
    const int e0  = es * 512;
    const int dg  = tid & 7;
    const int bg  = tid >> 3;

    __shared__ float Ws[32][33];
    __shared__ float Cs[64][33];

    float acc[4][4];
#pragma unroll
    for (int i = 0; i < 4; i++)
#pragma unroll
        for (int j = 0; j < 4; j++) acc[i][j] = 0.f;

    for (int ec = 0; ec < 512; ec += 32) {
#pragma unroll
        for (int i = 0; i < 8; i++) {
            int idx = tid + i * 128;
            int r = idx >> 5, c = idx & 31;
            Ws[r][c] = W[(size_t)(d0 + r) * (2 * DD) + e0 + ec + c];
        }
#pragma unroll
        for (int i = 0; i < 16; i++) {
            int idx = tid + i * 128;
            int r = idx >> 5, c = idx & 31;
            Cs[r][c] = g_comb[(size_t)r * (2 * DD) + e0 + ec + c];
        }
        __syncthreads();
#pragma unroll
        for (int k = 0; k < 32; k++) {
            float wv[4], cvv[4];
#pragma unroll
            for (int j = 0; j < 4; j++) wv[j] = Ws[dg + 8 * j][k];
#pragma unroll
            for (int i = 0; i < 4; i++) cvv[i] = Cs[bg + 16 * i][k];
#pragma unroll
            for (int i = 0; i < 4; i++)
#pragma unroll
                for (int j = 0; j < 4; j++)
                    acc[i][j] = fmaf(cvv[i], wv[j], acc[i][j]);
        }
        __syncthreads();
    }

#pragma unroll
    for (int i = 0; i < 4; i++)
#pragma unroll
        for (int j = 0; j < 4; j++) {
            int bidx = bg + 16 * i;
            int didx = d0 + dg + 8 * j;
            g_out_part[(size_t)es * BB * DD + (size_t)bidx * DD + didx] =
                acc[i][j];
        }
}

// ---------------------------------------------------------------------------
// Kernel 4: sum e-split partials + bias, tanh, write out
// ---------------------------------------------------------------------------
__global__ void k4_final(const float* __restrict__ bias,
                         float* __restrict__ out) {
    const int idx = blockIdx.x * blockDim.x + threadIdx.x;
    const int d = idx & (DD - 1);
    float a = bias[d];
#pragma unroll
    for (int es = 0; es < ESPLIT; es++)
        a += g_out_part[(size_t)es * BB * DD + idx];
    out[idx] = tanhf(a);
}

// ---------------------------------------------------------------------------
extern "C" void kernel_launch(void* const* d_in, const int* in_sizes, int n_in,
                              void* d_out, int out_size) {
    const float* output  = (const float*)d_in[0];  // (64,1,1024)
    const float* context = (const float*)d_in[1];  // (64,2048,1024)
    const float* W_out   = (const float*)d_in[2];  // (1024,2048)
    const float* b_out   = (const float*)d_in[3];  // (1024)

    float* out  = (float*)d_out;       // (64,1,1024) first
    float* attn = out + BB * DD;       // (64,1,2048) second

    static int smem_set = 0;
    if (!smem_set) {
        cudaFuncSetAttribute(k1_scores_mix,
                             cudaFuncAttributeMaxDynamicSharedMemorySize,
                             SMEM_K1);
        smem_set = 1;
    }

    k1_scores_mix<<<dim3(SPLIT, BB), 256, SMEM_K1>>>(output, context);
    k2_combine<<<BB, 256>>>(output, attn);
    k3_gemm<<<dim3(32, ESPLIT), 128>>>(W_out);
    k4_final<<<256, 256>>>(b_out, out);
}

// round 3
// speedup vs baseline: 1.1545x; 1.1545x over previous
#include <cuda_runtime.h>
#include <cuda_bf16.h>

#define BB 64
#define NN 2048
#define DD 1024
#define SPLIT 32
#define ROWS_BLK (NN / SPLIT)   // 64 rows per block
#define ROWS_W 8                // rows per warp
#define SBUF 3                  // per-warp ring depth
#define ESPLIT 16

#define SMEM_K1 (8 * SBUF * DD * 4)   // 8 warps * 3 slots * 4KB = 98304 B

// Scratch (static device globals; no allocation)
__device__ float g_scores[BB * NN];
__device__ float g_part_m[BB * SPLIT];
__device__ float g_part_l[BB * SPLIT];
__device__ float g_part_mix[BB * SPLIT * DD];
__device__ float g_comb[BB * 2 * DD];            // [mix | output]
__device__ float g_out_part[ESPLIT * BB * DD];   // 4 MB GEMM partials

__device__ __forceinline__ unsigned smem_u32(const void* p) {
    return (unsigned)__cvta_generic_to_shared(p);
}

// One 4KB row: 256 16B chunks spread over 32 lanes (contiguous per instr).
__device__ __forceinline__ void issue_row(float* dst, const float* src,
                                          int lane) {
#pragma unroll
    for (int c = 0; c < 8; c++) {
        const int f = (c * 32 + lane) * 4;   // float index
        unsigned sa = smem_u32(dst + f);
        asm volatile("cp.async.cg.shared.global [%0], [%1], 16;\n"
                     :: "r"(sa), "l"(src + f));
    }
}

// ---------------------------------------------------------------------------
// Kernel 1: barrier-free per-warp cp.async pipelines.
// grid (SPLIT, BB), 256 threads. Warp w owns rows [w*8, w*8+8) and a private
// 3-slot smem ring. No __syncthreads until the final block combine.
// ---------------------------------------------------------------------------
__global__ __launch_bounds__(256, 2)
void k1_scores_mix(const float* __restrict__ output,
                   const float* __restrict__ context) {
    extern __shared__ float smem[];          // 8 * SBUF * DD floats
    __shared__ float sm[8], sl[8];

    const int split = blockIdx.x;
    const int b     = blockIdx.y;
    const int tid   = threadIdx.x;
    const int w     = tid >> 5;
    const int lane  = tid & 31;

    const float* q   = output + (size_t)b * DD;
    const float* ctx = context + (size_t)b * NN * DD
                               + (size_t)(split * ROWS_BLK + w * ROWS_W) * DD;
    float* ring = smem + w * (SBUF * DD);

    float4 qv[8];
#pragma unroll
    for (int j = 0; j < 8; j++)
        qv[j] = *(const float4*)(q + j * 128 + lane * 4);

    float acc[32];
#pragma unroll
    for (int k = 0; k < 32; k++) acc[k] = 0.f;
    float m = -1e30f, l = 0.f;

    // Prologue: rows 0,1 in flight
#pragma unroll
    for (int ps = 0; ps < SBUF - 1; ps++) {
        issue_row(ring + ps * DD, ctx + (size_t)ps * DD, lane);
        asm volatile("cp.async.commit_group;\n");
    }

#pragma unroll
    for (int r = 0; r < ROWS_W; r++) {
        asm volatile("cp.async.wait_group 1;\n");
        __syncwarp();

        // Refill slot (r+2)%3 (last read two iterations ago) immediately.
        if (r + SBUF - 1 < ROWS_W)
            issue_row(ring + ((r + SBUF - 1) % SBUF) * DD,
                      ctx + (size_t)(r + SBUF - 1) * DD, lane);
        asm volatile("cp.async.commit_group;\n");

        const float* row = ring + (r % SBUF) * DD;
        float4 cv[8];
#pragma unroll
        for (int j = 0; j < 8; j++)
            cv[j] = *(const float4*)(row + j * 128 + lane * 4);

        float s0 = 0.f, s1 = 0.f, s2 = 0.f, s3 = 0.f;
#pragma unroll
        for (int j = 0; j < 8; j++) {
            s0 = fmaf(qv[j].x, cv[j].x, s0);
            s1 = fmaf(qv[j].y, cv[j].y, s1);
            s2 = fmaf(qv[j].z, cv[j].z, s2);
            s3 = fmaf(qv[j].w, cv[j].w, s3);
        }
        float s = (s0 + s1) + (s2 + s3);
#pragma unroll
        for (int off = 16; off; off >>= 1)
            s += __shfl_xor_sync(0xffffffffu, s, off);

        if (lane == 0)
            g_scores[(size_t)b * NN + split * ROWS_BLK + w * ROWS_W + r] = s;

        // Branchy online softmax (s warp-uniform -> no divergence)
        if (s <= m) {
            const float p = __expf(s - m);
            l += p;
#pragma unroll
            for (int j = 0; j < 8; j++) {
                acc[4 * j + 0] = fmaf(p, cv[j].x, acc[4 * j + 0]);
                acc[4 * j + 1] = fmaf(p, cv[j].y, acc[4 * j + 1]);
                acc[4 * j + 2] = fmaf(p, cv[j].z, acc[4 * j + 2]);
                acc[4 * j + 3] = fmaf(p, cv[j].w, acc[4 * j + 3]);
            }
        } else {
            const float c = __expf(m - s);
            l = fmaf(l, c, 1.f);
#pragma unroll
            for (int j = 0; j < 8; j++) {
                acc[4 * j + 0] = fmaf(acc[4 * j + 0], c, cv[j].x);
                acc[4 * j + 1] = fmaf(acc[4 * j + 1], c, cv[j].y);
                acc[4 * j + 2] = fmaf(acc[4 * j + 2], c, cv[j].z);
                acc[4 * j + 3] = fmaf(acc[4 * j + 3], c, cv[j].w);
            }
            m = s;
        }
    }

    // Drain all async groups, then block combine (one barrier).
    asm volatile("cp.async.wait_group 0;\n");
    if (lane == 0) { sm[w] = m; sl[w] = l; }
    __syncthreads();

    float M = sm[0];
#pragma unroll
    for (int s2 = 1; s2 < 8; s2++) M = fmaxf(M, sm[s2]);
    float L = 0.f;
#pragma unroll
    for (int s2 = 0; s2 < 8; s2++) L += sl[s2] * __expf(sm[s2] - M);

    const float scale = __expf(m - M);
    float* red = smem;                       // reuse ring region: 8 * DD
#pragma unroll
    for (int j = 0; j < 8; j++) {
        float4 v = make_float4(acc[4 * j + 0] * scale, acc[4 * j + 1] * scale,
                               acc[4 * j + 2] * scale, acc[4 * j + 3] * scale);
        *(float4*)(red + w * DD + j * 128 + lane * 4) = v;
    }
    __syncthreads();

    {
        const int d0 = tid * 4;
        float4 r = *(const float4*)(red + d0);
#pragma unroll
        for (int ww = 1; ww < 8; ww++) {
            float4 v = *(const float4*)(red + ww * DD + d0);
            r.x += v.x; r.y += v.y; r.z += v.z; r.w += v.w;
        }
        const int ps = b * SPLIT + split;
        *(float4*)(&g_part_mix[(size_t)ps * DD + d0]) = r;
        if (tid == 0) { g_part_m[ps] = M; g_part_l[ps] = L; }
    }
}

// ---------------------------------------------------------------------------
// Kernel 2: combine splits -> final mix; build [mix|output]; write attn
// ---------------------------------------------------------------------------
__global__ void k2_combine(const float* __restrict__ output,
                           float* __restrict__ attn_out) {
    const int b   = blockIdx.x;
    const int tid = threadIdx.x;

    float M = -1e30f;
#pragma unroll
    for (int s = 0; s < SPLIT; s++) M = fmaxf(M, g_part_m[b * SPLIT + s]);
    float wgt[SPLIT];
    float L = 0.f;
#pragma unroll
    for (int s = 0; s < SPLIT; s++) {
        wgt[s] = __expf(g_part_m[b * SPLIT + s] - M);
        L += g_part_l[b * SPLIT + s] * wgt[s];
    }
    const float invL = 1.f / L;

    for (int d = tid; d < DD; d += blockDim.x) {
        float a = 0.f;
#pragma unroll
        for (int s = 0; s < SPLIT; s++)
            a += g_part_mix[(size_t)(b * SPLIT + s) * DD + d] * wgt[s];
        g_comb[(size_t)b * 2 * DD + d] = a * invL;
    }
    for (int d = tid; d < DD; d += blockDim.x)
        g_comb[(size_t)b * 2 * DD + DD + d] = output[(size_t)b * DD + d];
    for (int n = tid; n < NN; n += blockDim.x)
        attn_out[(size_t)b * NN + n] =
            __expf(g_scores[(size_t)b * NN + n] - M) * invL;
}

// ---------------------------------------------------------------------------
// Kernel 3: out_part = comb @ W^T. Block tile 64d x 64b x 128e,
// grid (16 dtiles, 16 esplits) = 256 blocks, 256 threads, 4x4 reg tile.
// ---------------------------------------------------------------------------
__global__ __launch_bounds__(256)
void k3_gemm(const float* __restrict__ W) {
    const int dt  = blockIdx.x;
    const int es  = blockIdx.y;
    const int tid = threadIdx.x;
    const int d0  = dt * 64;
    const int e0  = es * 128;
    const int dg  = tid & 15;
    const int bg  = tid >> 4;

    __shared__ float Ws[64][33];
    __shared__ float Cs[64][33];

    float acc[4][4];
#pragma unroll
    for (int i = 0; i < 4; i++)
#pragma unroll
        for (int j = 0; j < 4; j++) acc[i][j] = 0.f;

    for (int ec = 0; ec < 128; ec += 32) {
#pragma unroll
        for (int i = 0; i < 8; i++) {
            int idx = tid + i * 256;
            int r = idx >> 5, c = idx & 31;
            Ws[r][c] = W[(size_t)(d0 + r) * (2 * DD) + e0 + ec + c];
            Cs[r][c] = g_comb[(size_t)r * (2 * DD) + e0 + ec + c];
        }
        __syncthreads();
#pragma unroll
        for (int k = 0; k < 32; k++) {
            float wv[4], cvv[4];
#pragma unroll
            for (int j = 0; j < 4; j++) wv[j] = Ws[dg + 16 * j][k];
#pragma unroll
            for (int i = 0; i < 4; i++) cvv[i] = Cs[bg + 16 * i][k];
#pragma unroll
            for (int i = 0; i < 4; i++)
#pragma unroll
                for (int j = 0; j < 4; j++)
                    acc[i][j] = fmaf(cvv[i], wv[j], acc[i][j]);
        }
        __syncthreads();
    }

#pragma unroll
    for (int i = 0; i < 4; i++)
#pragma unroll
        for (int j = 0; j < 4; j++) {
            int bidx = bg + 16 * i;
            int didx = d0 + dg + 16 * j;
            g_out_part[(size_t)es * BB * DD + (size_t)bidx * DD + didx] =
                acc[i][j];
        }
}

// ---------------------------------------------------------------------------
// Kernel 4: sum e-split partials + bias, HW tanh, write out
// ---------------------------------------------------------------------------
__global__ void k4_final(const float* __restrict__ bias,
                         float* __restrict__ out) {
    const int idx = blockIdx.x * blockDim.x + threadIdx.x;  // 0..65535
    const int d = idx & (DD - 1);
    float a = bias[d];
#pragma unroll
    for (int es = 0; es < ESPLIT; es++)
        a += g_out_part[(size_t)es * BB * DD + idx];
    float r;
    asm("tanh.approx.f32 %0, %1;" : "=f"(r) : "f"(a));
    out[idx] = r;
}

// ---------------------------------------------------------------------------
extern "C" void kernel_launch(void* const* d_in, const int* in_sizes, int n_in,
                              void* d_out, int out_size) {
    const float* output  = (const float*)d_in[0];  // (64,1,1024)
    const float* context = (const float*)d_in[1];  // (64,2048,1024)
    const float* W_out   = (const float*)d_in[2];  // (1024,2048)
    const float* b_out   = (const float*)d_in[3];  // (1024)

    float* out  = (float*)d_out;       // (64,1,1024) first
    float* attn = out + BB * DD;       // (64,1,2048) second

    static int smem_set = 0;
    if (!smem_set) {
        cudaFuncSetAttribute(k1_scores_mix,
                             cudaFuncAttributeMaxDynamicSharedMemorySize,
                             SMEM_K1);
        smem_set = 1;
    }

    k1_scores_mix<<<dim3(SPLIT, BB), 256, SMEM_K1>>>(output, context);
    k2_combine<<<BB, 256>>>(output, attn);
    k3_gemm<<<dim3(16, ESPLIT), 256>>>(W_out);
    k4_final<<<256, 256>>>(b_out, out);
}